// round 12
// baseline (speedup 1.0000x reference)
#include <cuda_runtime.h>
#include <cuda_bf16.h>
#include <math.h>
#include <cstdint>

#define SDIM 4096
#define CDIM 256
#define EDIM 128
#define NBATCH 4

// ---- scratch (device globals: allocation-free) ----
// tp rows = spatial s/t, 512 cols: [0:128)=theta, [128:256)=phi, [256:512)=xp^T (= (proj_w@x)[o,t])
__device__ __nv_bfloat16 g_tp[(size_t)NBATCH * SDIM * 512];
__device__ __nv_bfloat16 g_f [(size_t)NBATCH * SDIM * SDIM];       // unnormalized exp(logits)
__device__ __nv_bfloat16 g_w2[512 * 256];                          // rows: 0-127 theta_w, 128-255 phi_w, 256-511 proj_w
__device__ float         g_Z [(size_t)NBATCH * SDIM];              // row sums

// ============================ low-level helpers ============================
__device__ __forceinline__ uint32_t smem_u32(const void* p) {
    uint32_t a;
    asm("{ .reg .u64 t; cvta.to.shared.u64 t, %1; cvt.u32.u64 %0, t; }" : "=r"(a) : "l"(p));
    return a;
}
__device__ __forceinline__ void ldsm4(uint32_t r[4], uint32_t addr) {
    asm volatile("ldmatrix.sync.aligned.m8n8.x4.shared.b16 {%0,%1,%2,%3}, [%4];"
                 : "=r"(r[0]), "=r"(r[1]), "=r"(r[2]), "=r"(r[3]) : "r"(addr));
}
__device__ __forceinline__ void ldsm4t(uint32_t r[4], uint32_t addr) {
    asm volatile("ldmatrix.sync.aligned.m8n8.x4.trans.shared.b16 {%0,%1,%2,%3}, [%4];"
                 : "=r"(r[0]), "=r"(r[1]), "=r"(r[2]), "=r"(r[3]) : "r"(addr));
}
__device__ __forceinline__ void mma16816(float c[4], const uint32_t a[4], uint32_t b0, uint32_t b1) {
    asm volatile("mma.sync.aligned.m16n8k16.row.col.f32.bf16.bf16.f32 "
                 "{%0,%1,%2,%3},{%4,%5,%6,%7},{%8,%9},{%0,%1,%2,%3};"
                 : "+f"(c[0]), "+f"(c[1]), "+f"(c[2]), "+f"(c[3])
                 : "r"(a[0]), "r"(a[1]), "r"(a[2]), "r"(a[3]), "r"(b0), "r"(b1));
}
__device__ __forceinline__ void cp16(uint32_t saddr, const void* g) {
    asm volatile("cp.async.cg.shared.global [%0], [%1], 16;" :: "r"(saddr), "l"(g));
}
#define CP_COMMIT() asm volatile("cp.async.commit_group;" ::: "memory")
#define CP_WAIT(N)  asm volatile("cp.async.wait_group %0;" :: "n"(N) : "memory")

__device__ __forceinline__ uint32_t bfbits(__nv_bfloat162 h) {
    return *reinterpret_cast<uint32_t*>(&h);
}
__device__ __forceinline__ void sts128(uint32_t addr, uint32_t v0, uint32_t v1, uint32_t v2, uint32_t v3) {
    asm volatile("st.shared.v4.b32 [%0], {%1,%2,%3,%4};"
                 :: "r"(addr), "r"(v0), "r"(v1), "r"(v2), "r"(v3) : "memory");
}
__device__ __forceinline__ void lds128(uint32_t addr, float& a, float& b, float& c, float& d) {
    asm volatile("ld.shared.v4.f32 {%0,%1,%2,%3}, [%4];"
                 : "=f"(a), "=f"(b), "=f"(c), "=f"(d) : "r"(addr));
}

// R rows x 64 cols bf16 (128B rows), XOR-16B swizzle keyed on row&7. NT threads.
template<int R, int NT>
__device__ __forceinline__ void load_tileT(uint32_t sdst, const __nv_bfloat16* g, int ldg) {
    const int tid = threadIdx.x;
    #pragma unroll
    for (int i = 0; i < (R * 8) / NT; i++) {
        const int c = tid + i * NT;
        const int r = c >> 3, kc = c & 7;
        const uint32_t so = sdst + r * 128 + (((uint32_t)kc * 16) ^ ((r & 7) * 16));
        cp16(so, g + (size_t)r * ldg + kc * 8);
    }
}
// 64 rows x 128 cols bf16 (256B rows), 256 threads (trans-A operand tile, bf16 source).
__device__ __forceinline__ void load_tile_64x128(uint32_t sdst, const __nv_bfloat16* g, int ldg) {
    const int tid = threadIdx.x;
    #pragma unroll
    for (int i = 0; i < 4; i++) {
        const int c = tid + i * 256;
        const int r = c >> 4, kc = c & 15;
        const uint32_t so = sdst + r * 256 + (((uint32_t)kc * 16) ^ ((r & 7) * 16));
        cp16(so, g + (size_t)r * ldg + kc * 8);
    }
}
// 64 rows x 128 cols fp32 (512B rows) staging load, 256 threads, XOR-16B swizzle on row&7.
__device__ __forceinline__ void load_stage_f32(uint32_t sdst, const float* g, int ldg) {
    const int tid = threadIdx.x;
    #pragma unroll
    for (int i = 0; i < 8; i++) {
        const int c = tid + i * 256;           // 0..2047 chunks of 16B
        const int r = c >> 5, kc = c & 31;     // row 0..63, 16B-chunk 0..31
        const uint32_t so = sdst + r * 512 + (((uint32_t)kc * 16) ^ ((r & 7) * 16));
        cp16(so, g + (size_t)r * ldg + kc * 4);
    }
}
// convert fp32 staging (64x128, 512B rows, swizzled) -> bf16 tile (64x128, 256B rows, swizzled)
__device__ __forceinline__ void convert_stage(uint32_t sstage, uint32_t sdst) {
    const int tid = threadIdx.x;
    #pragma unroll
    for (int i = 0; i < 4; i++) {
        const int c = tid + i * 256;           // 0..1023 output 16B chunks
        const int r = c >> 4;                  // row 0..63
        const int oc = c & 15;                 // output chunk (8 bf16)
        const int kc = oc * 2;                 // input chunks (2 x 4 fp32)
        const uint32_t xr = (uint32_t)((r & 7) * 16);
        float f0, f1, f2, f3, f4, f5, f6, f7;
        lds128(sstage + r * 512 + (((uint32_t)kc * 16) ^ xr), f0, f1, f2, f3);
        lds128(sstage + r * 512 + (((uint32_t)(kc + 1) * 16) ^ xr), f4, f5, f6, f7);
        const uint32_t v0 = bfbits(__floats2bfloat162_rn(f0, f1));
        const uint32_t v1 = bfbits(__floats2bfloat162_rn(f2, f3));
        const uint32_t v2 = bfbits(__floats2bfloat162_rn(f4, f5));
        const uint32_t v3 = bfbits(__floats2bfloat162_rn(f6, f7));
        sts128(sdst + r * 256 + (((uint32_t)oc * 16) ^ xr), v0, v1, v2, v3);
    }
}

// ---- 64x32 warp-tile chunk (regular A) ----
__device__ __forceinline__ void compute_chunk(uint32_t sA, uint32_t sB,
                                              int m_base, int n_base, int lane,
                                              float acc[4][4][4]) {
    #pragma unroll
    for (int ks = 0; ks < 4; ks++) {
        const int kc = ks * 2 + (lane >> 4);
        uint32_t a[4][4];
        #pragma unroll
        for (int mi = 0; mi < 4; mi++) {
            const int row = m_base + mi * 16 + (lane & 15);
            ldsm4(a[mi], sA + row * 128 + (((uint32_t)kc * 16) ^ ((row & 7) * 16)));
        }
        uint32_t b[4][2];
        #pragma unroll
        for (int nh = 0; nh < 2; nh++) {
            const int row = n_base + nh * 16 + (lane & 15);
            uint32_t r4[4];
            ldsm4(r4, sB + row * 128 + (((uint32_t)kc * 16) ^ ((row & 7) * 16)));
            b[nh * 2 + 0][0] = r4[0]; b[nh * 2 + 0][1] = r4[2];
            b[nh * 2 + 1][0] = r4[1]; b[nh * 2 + 1][1] = r4[3];
        }
        #pragma unroll
        for (int mi = 0; mi < 4; mi++)
            #pragma unroll
            for (int ni = 0; ni < 4; ni++)
                mma16816(acc[mi][ni], a[mi], b[ni][0], b[ni][1]);
    }
}

// ---- trans-A chunk: A stored [k][m] (64 rows x 128 cols, 256B rows), B regular [n][k] ----
__device__ __forceinline__ void compute_chunk_At(uint32_t sA, uint32_t sB,
                                                 int wm, int wn, int lane,
                                                 float acc[4][4][4]) {
    #pragma unroll
    for (int ks = 0; ks < 4; ks++) {
        uint32_t a[4][4];
        const int crow_l = ks * 16 + (lane & 7) + ((lane >> 4) & 1) * 8;
        #pragma unroll
        for (int mi = 0; mi < 4; mi++) {
            const int scol = wm * 64 + mi * 16 + ((lane >> 3) & 1) * 8;
            ldsm4t(a[mi], sA + crow_l * 256 + ((((uint32_t)scol >> 3) * 16) ^ ((crow_l & 7) * 16)));
        }
        const int kc = ks * 2 + (lane >> 4);
        uint32_t b[4][2];
        #pragma unroll
        for (int nh = 0; nh < 2; nh++) {
            const int row = wn * 32 + nh * 16 + (lane & 15);
            uint32_t r4[4];
            ldsm4(r4, sB + row * 128 + (((uint32_t)kc * 16) ^ ((row & 7) * 16)));
            b[nh * 2 + 0][0] = r4[0]; b[nh * 2 + 0][1] = r4[2];
            b[nh * 2 + 1][0] = r4[1]; b[nh * 2 + 1][1] = r4[3];
        }
        #pragma unroll
        for (int mi = 0; mi < 4; mi++)
            #pragma unroll
            for (int ni = 0; ni < 4; ni++)
                mma16816(acc[mi][ni], a[mi], b[ni][0], b[ni][1]);
    }
}

#define ZERO_ACC4(acc) do { \
    _Pragma("unroll") for (int _a = 0; _a < 4; _a++) \
    _Pragma("unroll") for (int _b = 0; _b < 4; _b++) \
    _Pragma("unroll") for (int _c = 0; _c < 4; _c++) acc[_a][_b][_c] = 0.0f; } while (0)

// ============================ tiny prep: weights -> bf16, Z -> 0 ============================
__global__ __launch_bounds__(256) void prep_w(const float4* __restrict__ theta_w,
                                              const float4* __restrict__ phi_w,
                                              const float4* __restrict__ proj_w,
                                              uint2* __restrict__ w2,
                                              float* __restrict__ Z)
{
    const int gt = blockIdx.x * blockDim.x + threadIdx.x;   // 64 blocks x 256 = 16384
    Z[gt] = 0.0f;                                            // NBATCH*SDIM = 16384 exactly
    if (gt < 8192) {        // theta_w, phi_w: 128x256 each = 8192 float4
        float4 v = theta_w[gt];
        __nv_bfloat162 a = __floats2bfloat162_rn(v.x, v.y);
        __nv_bfloat162 b = __floats2bfloat162_rn(v.z, v.w);
        w2[gt] = make_uint2(*reinterpret_cast<uint32_t*>(&a), *reinterpret_cast<uint32_t*>(&b));
        v = phi_w[gt];
        a = __floats2bfloat162_rn(v.x, v.y);
        b = __floats2bfloat162_rn(v.z, v.w);
        w2[8192 + gt] = make_uint2(*reinterpret_cast<uint32_t*>(&a), *reinterpret_cast<uint32_t*>(&b));
    }
    // proj_w: 256x256 = 16384 float4 -> w2 rows 256-511
    {
        float4 v = proj_w[gt];
        __nv_bfloat162 a = __floats2bfloat162_rn(v.x, v.y);
        __nv_bfloat162 b = __floats2bfloat162_rn(v.z, v.w);
        w2[16384 + gt] = make_uint2(*reinterpret_cast<uint32_t*>(&a), *reinterpret_cast<uint32_t*>(&b));
    }
}

// ============================ projections (HMMA trans-A, cp.async fp32 staging + smem convert) ============================
// tp[s][o] = sum_c x[c,s] * w2[o,c]. theta (o 0-127), phi (128-255), xp^T (256-511).
// smem: STAGE fp32 @0 (32KB), ABF @32768 (16KB), B0 @49152, B1 @65536 (16KB each) = 80KB.
#define PJ_STAGE 0u
#define PJ_ABF   32768u
#define PJ_B(st) ((uint32_t)(49152 + (st) * 16384))
__global__ __launch_bounds__(256)
void projections_hmma(const float* __restrict__ x,
                      const __nv_bfloat16* __restrict__ w2,
                      __nv_bfloat16* __restrict__ tp)
{
    extern __shared__ char smem[];
    const uint32_t sb = smem_u32(smem);
    const int tid = threadIdx.x, lane = tid & 31, wid = tid >> 5;
    const int wm = wid & 1, wn = wid >> 1;
    const int z = blockIdx.z, m0 = blockIdx.y * 128, n0 = blockIdx.x * 128;

    const float* Abase = x + (size_t)z * CDIM * SDIM + m0;   // rows c (K), cols s; ld SDIM, fp32
    const __nv_bfloat16* Bbase = w2 + (size_t)n0 * 256;

    float acc[4][4][4];
    ZERO_ACC4(acc);

    // prologue: stage fp32 A chunk 0 + B chunk 0
    load_stage_f32(sb + PJ_STAGE, Abase, SDIM);
    load_tileT<128, 256>(sb + PJ_B(0), Bbase, 256);
    CP_COMMIT();

    const int KT = 4;
    #pragma unroll
    for (int kt = 0; kt < KT; kt++) {
        CP_WAIT(0);          // stage kt + B kt arrived (and prior compute done via this sync)
        __syncthreads();
        convert_stage(sb + PJ_STAGE, sb + PJ_ABF);
        __syncthreads();     // ABF complete, STAGE free
        if (kt + 1 < KT) {   // prefetch next chunk; overlaps compute below
            load_stage_f32(sb + PJ_STAGE, Abase + (size_t)(kt + 1) * 64 * SDIM, SDIM);
            load_tileT<128, 256>(sb + PJ_B((kt + 1) & 1), Bbase + (kt + 1) * 64, 256);
            CP_COMMIT();
        }
        compute_chunk_At(sb + PJ_ABF, sb + PJ_B(kt & 1), wm, wn, lane, acc);
    }

    const int lrow = lane >> 2, lcol2 = (lane & 3) * 2;
    #pragma unroll
    for (int mi = 0; mi < 4; mi++) {
        const int gr0 = m0 + wm * 64 + mi * 16 + lrow;   // s
        #pragma unroll
        for (int ni = 0; ni < 4; ni++) {
            const int col = n0 + wn * 32 + ni * 8 + lcol2;  // o in [0,512)
            __nv_bfloat162 h0 = __floats2bfloat162_rn(acc[mi][ni][0], acc[mi][ni][1]);
            __nv_bfloat162 h1 = __floats2bfloat162_rn(acc[mi][ni][2], acc[mi][ni][3]);
            *reinterpret_cast<uint32_t*>(tp + ((size_t)z * SDIM + gr0) * 512 + col) =
                *reinterpret_cast<uint32_t*>(&h0);
            *reinterpret_cast<uint32_t*>(tp + ((size_t)z * SDIM + gr0 + 8) * 512 + col) =
                *reinterpret_cast<uint32_t*>(&h1);
        }
    }
}

// ============================ fused logits + exp (R9-proven shape, ld=512) ============================
#define SA2(st) ((uint32_t)((st) * 32768))
#define SB2(st) ((uint32_t)((st) * 32768 + 16384))
__global__ __launch_bounds__(256)
void logits_exp_hmma(const __nv_bfloat16* __restrict__ tp,
                     __nv_bfloat16* __restrict__ f,
                     float* __restrict__ Z)
{
    extern __shared__ char smem[];
    const uint32_t sb = smem_u32(smem);
    const int tid = threadIdx.x, lane = tid & 31, wid = tid >> 5;
    const int wm = wid & 1, wn = wid >> 1;
    const int z = blockIdx.z, m0 = blockIdx.y * 128, n0 = blockIdx.x * 128;

    const __nv_bfloat16* Abase = tp + ((size_t)(z * SDIM + m0)) * 512;        // theta
    const __nv_bfloat16* Bbase = tp + ((size_t)(z * SDIM + n0)) * 512 + 128;  // phi

    float acc[4][4][4];
    ZERO_ACC4(acc);

    load_tileT<128, 256>(sb + SA2(0), Abase, 512);
    load_tileT<128, 256>(sb + SB2(0), Bbase, 512);
    CP_COMMIT();
    load_tileT<128, 256>(sb + SA2(1), Abase + 64, 512);
    load_tileT<128, 256>(sb + SB2(1), Bbase + 64, 512);
    CP_COMMIT();

    CP_WAIT(1);
    __syncthreads();
    compute_chunk(sb + SA2(0), sb + SB2(0), wm * 64, wn * 32, lane, acc);
    CP_WAIT(0);
    __syncthreads();
    compute_chunk(sb + SA2(1), sb + SB2(1), wm * 64, wn * 32, lane, acc);

    const float alpha = 0.08838834764831845f; // 1/sqrt(128)
    const int lrow = lane >> 2, lcol2 = (lane & 3) * 2;
    #pragma unroll
    for (int mi = 0; mi < 4; mi++) {
        const int gr0 = m0 + wm * 64 + mi * 16 + lrow;
        const int gr1 = gr0 + 8;
        float rs0 = 0.0f, rs1 = 0.0f;
        #pragma unroll
        for (int ni = 0; ni < 4; ni++) {
            const int col = n0 + wn * 32 + ni * 8 + lcol2;
            float e00 = __expf(acc[mi][ni][0] * alpha);
            float e01 = __expf(acc[mi][ni][1] * alpha);
            float e10 = __expf(acc[mi][ni][2] * alpha);
            float e11 = __expf(acc[mi][ni][3] * alpha);
            rs0 += e00 + e01; rs1 += e10 + e11;
            __nv_bfloat162 h0 = __floats2bfloat162_rn(e00, e01);
            __nv_bfloat162 h1 = __floats2bfloat162_rn(e10, e11);
            *reinterpret_cast<uint32_t*>(f + ((size_t)z * SDIM + gr0) * SDIM + col) =
                *reinterpret_cast<uint32_t*>(&h0);
            *reinterpret_cast<uint32_t*>(f + ((size_t)z * SDIM + gr1) * SDIM + col) =
                *reinterpret_cast<uint32_t*>(&h1);
        }
        rs0 += __shfl_xor_sync(0xffffffffu, rs0, 1);
        rs0 += __shfl_xor_sync(0xffffffffu, rs0, 2);
        rs1 += __shfl_xor_sync(0xffffffffu, rs1, 1);
        rs1 += __shfl_xor_sync(0xffffffffu, rs1, 2);
        if ((lane & 3) == 0) {
            atomicAdd(&Z[(size_t)z * SDIM + gr0], rs0);
            atomicAdd(&Z[(size_t)z * SDIM + gr1], rs1);
        }
    }
}

// ============================ fused attend+proj (R9-proven, trans-A HMMA, 3-stage) ============================
// out[n][o][s] = x[n][o][s] + (1/Z[s]) * sum_t xp[o,t] * f[s,t]
#define ASA(st) ((uint32_t)((st) * 32768))
#define ASB(st) ((uint32_t)((st) * 32768 + 16384))
__global__ __launch_bounds__(256)
void attend_proj_hmma(const __nv_bfloat16* __restrict__ tp,
                      const __nv_bfloat16* __restrict__ f,
                      const float* __restrict__ Z,
                      const float* __restrict__ x,
                      float* __restrict__ out)
{
    extern __shared__ char smem[];
    const uint32_t sb = smem_u32(smem);
    const int tid = threadIdx.x, lane = tid & 31, wid = tid >> 5;
    const int wm = wid & 1, wn = wid >> 1;
    const int z = blockIdx.z, m0 = blockIdx.y * 128, n0 = blockIdx.x * 128;

    const __nv_bfloat16* Abase = tp + (size_t)z * SDIM * 512 + 256 + m0;   // rows t, ld 512
    const __nv_bfloat16* Bbase = f + ((size_t)z * SDIM + n0) * SDIM;       // rows s, ld SDIM

    float acc[4][4][4];
    ZERO_ACC4(acc);

    load_tile_64x128(sb + ASA(0), Abase, 512);
    load_tileT<128, 256>(sb + ASB(0), Bbase, SDIM);
    CP_COMMIT();
    load_tile_64x128(sb + ASA(1), Abase + (size_t)64 * 512, 512);
    load_tileT<128, 256>(sb + ASB(1), Bbase + 64, SDIM);
    CP_COMMIT();

    const int KT = SDIM / 64; // 64
    for (int kt = 0; kt < KT; kt++) {
        if (kt + 1 < KT) { CP_WAIT(1); } else { CP_WAIT(0); }
        __syncthreads();
        if (kt + 2 < KT) {
            const int st = (kt + 2) % 3;
            load_tile_64x128(sb + ASA(st), Abase + (size_t)(kt + 2) * 64 * 512, 512);
            load_tileT<128, 256>(sb + ASB(st), Bbase + (kt + 2) * 64, SDIM);
            CP_COMMIT();
        }
        compute_chunk_At(sb + ASA(kt % 3), sb + ASB(kt % 3), wm, wn, lane, acc);
    }

    // epilogue: rows = o, cols = s; scale by 1/Z[s], add residual x, fp32 out
    const int lrow = lane >> 2, lcol2 = (lane & 3) * 2;
    #pragma unroll
    for (int ni = 0; ni < 4; ni++) {
        const int col = n0 + wn * 32 + ni * 8 + lcol2;   // s (even)
        const float2 zc = *reinterpret_cast<const float2*>(&Z[(size_t)z * SDIM + col]);
        const float izx = 1.0f / zc.x, izy = 1.0f / zc.y;
        #pragma unroll
        for (int mi = 0; mi < 4; mi++) {
            const int gr0 = m0 + wm * 64 + mi * 16 + lrow;   // o
            const int gr1 = gr0 + 8;
            const float2 x0 = *reinterpret_cast<const float2*>(x + ((size_t)z * CDIM + gr0) * SDIM + col);
            const float2 x1 = *reinterpret_cast<const float2*>(x + ((size_t)z * CDIM + gr1) * SDIM + col);
            float2 v0 = make_float2(acc[mi][ni][0] * izx + x0.x, acc[mi][ni][1] * izy + x0.y);
            float2 v1 = make_float2(acc[mi][ni][2] * izx + x1.x, acc[mi][ni][3] * izy + x1.y);
            *reinterpret_cast<float2*>(out + ((size_t)z * CDIM + gr0) * SDIM + col) = v0;
            *reinterpret_cast<float2*>(out + ((size_t)z * CDIM + gr1) * SDIM + col) = v1;
        }
    }
}

// ============================ launch ============================
extern "C" void kernel_launch(void* const* d_in, const int* in_sizes, int n_in,
                              void* d_out, int out_size)
{
    const float* x       = (const float*)d_in[0];
    const float* theta_w = (const float*)d_in[1];
    const float* phi_w   = (const float*)d_in[2];
    const float* proj_w  = (const float*)d_in[3];
    float* out = (float*)d_out;

    __nv_bfloat16 *tp, *f, *w2;
    float *Z;
    cudaGetSymbolAddress((void**)&tp, g_tp);
    cudaGetSymbolAddress((void**)&f,  g_f);
    cudaGetSymbolAddress((void**)&w2, g_w2);
    cudaGetSymbolAddress((void**)&Z,  g_Z);

    cudaFuncSetAttribute(projections_hmma, cudaFuncAttributeMaxDynamicSharedMemorySize, 81920);
    cudaFuncSetAttribute(logits_exp_hmma,  cudaFuncAttributeMaxDynamicSharedMemorySize, 65536);
    cudaFuncSetAttribute(attend_proj_hmma, cudaFuncAttributeMaxDynamicSharedMemorySize, 98304);

    // 0: weights -> bf16, Z -> 0 (tiny)
    prep_w<<<64, 256>>>((const float4*)theta_w, (const float4*)phi_w,
                        (const float4*)proj_w, (uint2*)w2, Z);

    // 1: all three projections (theta, phi, xp = proj_w @ x); fp32 x staged + converted in smem
    projections_hmma<<<dim3(4, 32, 4), 256, 81920>>>(x, w2, tp);

    // 2: fused logits -> exp + row sums (R9-proven shape)
    logits_exp_hmma<<<dim3(32, 32, 4), 256, 65536>>>(tp, f, Z);

    // 3: fused attend + projection + residual + 1/Z (R9-proven)
    attend_proj_hmma<<<dim3(32, 2, 4), 256, 98304>>>(tp, f, Z, x, out);
}

// round 13
// speedup vs baseline: 1.0491x; 1.0491x over previous
#include <cuda_runtime.h>
#include <cuda_fp16.h>
#include <math.h>
#include <cstdint>

#define SDIM 4096
#define CDIM 256
#define EDIM 128
#define NBATCH 4

// ---- scratch (device globals: allocation-free) ----
// tp rows = spatial s/t, 512 cols: [0:128)=theta, [128:256)=phi, [256:512)=xp^T (= (proj_w@x)[o,t])
__device__ __half g_tp[(size_t)NBATCH * SDIM * 512];
__device__ __half g_f [(size_t)NBATCH * SDIM * SDIM];       // unnormalized exp(logits)
__device__ __half g_xb[(size_t)NBATCH * CDIM * SDIM];       // x fp16 [n][c][s]
__device__ __half g_w2[512 * 256];                          // rows: 0-127 theta_w, 128-255 phi_w, 256-511 proj_w
__device__ float  g_Z [(size_t)NBATCH * SDIM];              // row sums

// ============================ low-level helpers ============================
__device__ __forceinline__ uint32_t smem_u32(const void* p) {
    uint32_t a;
    asm("{ .reg .u64 t; cvta.to.shared.u64 t, %1; cvt.u32.u64 %0, t; }" : "=r"(a) : "l"(p));
    return a;
}
__device__ __forceinline__ void ldsm4(uint32_t r[4], uint32_t addr) {
    asm volatile("ldmatrix.sync.aligned.m8n8.x4.shared.b16 {%0,%1,%2,%3}, [%4];"
                 : "=r"(r[0]), "=r"(r[1]), "=r"(r[2]), "=r"(r[3]) : "r"(addr));
}
__device__ __forceinline__ void ldsm4t(uint32_t r[4], uint32_t addr) {
    asm volatile("ldmatrix.sync.aligned.m8n8.x4.trans.shared.b16 {%0,%1,%2,%3}, [%4];"
                 : "=r"(r[0]), "=r"(r[1]), "=r"(r[2]), "=r"(r[3]) : "r"(addr));
}
// f16-accumulate HMMA: D(2 regs of f16x2) = A*B + D
__device__ __forceinline__ void mma16816h(uint32_t c[2], const uint32_t a[4], uint32_t b0, uint32_t b1) {
    asm volatile("mma.sync.aligned.m16n8k16.row.col.f16.f16.f16.f16 "
                 "{%0,%1},{%2,%3,%4,%5},{%6,%7},{%0,%1};"
                 : "+r"(c[0]), "+r"(c[1])
                 : "r"(a[0]), "r"(a[1]), "r"(a[2]), "r"(a[3]), "r"(b0), "r"(b1));
}
__device__ __forceinline__ void cp16(uint32_t saddr, const void* g) {
    asm volatile("cp.async.cg.shared.global [%0], [%1], 16;" :: "r"(saddr), "l"(g));
}
#define CP_COMMIT() asm volatile("cp.async.commit_group;" ::: "memory")
#define CP_WAIT(N)  asm volatile("cp.async.wait_group %0;" :: "n"(N) : "memory")

__device__ __forceinline__ uint32_t hbits(__half2 h) { return *reinterpret_cast<uint32_t*>(&h); }
__device__ __forceinline__ float2 h2f(uint32_t v) {
    __half2 h = *reinterpret_cast<__half2*>(&v);
    return __half22float2(h);
}

// R rows x 64 cols f16 (128B rows), XOR-16B swizzle keyed on row&7. NT threads.
template<int R, int NT>
__device__ __forceinline__ void load_tileT(uint32_t sdst, const __half* g, int ldg) {
    const int tid = threadIdx.x;
    #pragma unroll
    for (int i = 0; i < (R * 8) / NT; i++) {
        const int c = tid + i * NT;
        const int r = c >> 3, kc = c & 7;
        const uint32_t so = sdst + r * 128 + (((uint32_t)kc * 16) ^ ((r & 7) * 16));
        cp16(so, g + (size_t)r * ldg + kc * 8);
    }
}
// 64 rows x 128 cols f16 (256B rows), 256 threads (trans-A operand tile).
__device__ __forceinline__ void load_tile_64x128(uint32_t sdst, const __half* g, int ldg) {
    const int tid = threadIdx.x;
    #pragma unroll
    for (int i = 0; i < 4; i++) {
        const int c = tid + i * 256;
        const int r = c >> 4, kc = c & 15;
        const uint32_t so = sdst + r * 256 + (((uint32_t)kc * 16) ^ ((r & 7) * 16));
        cp16(so, g + (size_t)r * ldg + kc * 8);
    }
}

// ---- 64x32 warp-tile chunk (regular A), f16 accumulate ----
__device__ __forceinline__ void compute_chunk(uint32_t sA, uint32_t sB,
                                              int m_base, int n_base, int lane,
                                              uint32_t acc[4][4][2]) {
    #pragma unroll
    for (int ks = 0; ks < 4; ks++) {
        const int kc = ks * 2 + (lane >> 4);
        uint32_t a[4][4];
        #pragma unroll
        for (int mi = 0; mi < 4; mi++) {
            const int row = m_base + mi * 16 + (lane & 15);
            ldsm4(a[mi], sA + row * 128 + (((uint32_t)kc * 16) ^ ((row & 7) * 16)));
        }
        uint32_t b[4][2];
        #pragma unroll
        for (int nh = 0; nh < 2; nh++) {
            const int row = n_base + nh * 16 + (lane & 15);
            uint32_t r4[4];
            ldsm4(r4, sB + row * 128 + (((uint32_t)kc * 16) ^ ((row & 7) * 16)));
            b[nh * 2 + 0][0] = r4[0]; b[nh * 2 + 0][1] = r4[2];
            b[nh * 2 + 1][0] = r4[1]; b[nh * 2 + 1][1] = r4[3];
        }
        #pragma unroll
        for (int mi = 0; mi < 4; mi++)
            #pragma unroll
            for (int ni = 0; ni < 4; ni++)
                mma16816h(acc[mi][ni], a[mi], b[ni][0], b[ni][1]);
    }
}

// ---- trans-A chunk: A stored [k][m] (64 rows x 128 cols, 256B rows), B regular [n][k] ----
__device__ __forceinline__ void compute_chunk_At(uint32_t sA, uint32_t sB,
                                                 int wm, int wn, int lane,
                                                 uint32_t acc[4][4][2]) {
    #pragma unroll
    for (int ks = 0; ks < 4; ks++) {
        uint32_t a[4][4];
        const int crow_l = ks * 16 + (lane & 7) + ((lane >> 4) & 1) * 8;
        #pragma unroll
        for (int mi = 0; mi < 4; mi++) {
            const int scol = wm * 64 + mi * 16 + ((lane >> 3) & 1) * 8;
            ldsm4t(a[mi], sA + crow_l * 256 + ((((uint32_t)scol >> 3) * 16) ^ ((crow_l & 7) * 16)));
        }
        const int kc = ks * 2 + (lane >> 4);
        uint32_t b[4][2];
        #pragma unroll
        for (int nh = 0; nh < 2; nh++) {
            const int row = wn * 32 + nh * 16 + (lane & 15);
            uint32_t r4[4];
            ldsm4(r4, sB + row * 128 + (((uint32_t)kc * 16) ^ ((row & 7) * 16)));
            b[nh * 2 + 0][0] = r4[0]; b[nh * 2 + 0][1] = r4[2];
            b[nh * 2 + 1][0] = r4[1]; b[nh * 2 + 1][1] = r4[3];
        }
        #pragma unroll
        for (int mi = 0; mi < 4; mi++)
            #pragma unroll
            for (int ni = 0; ni < 4; ni++)
                mma16816h(acc[mi][ni], a[mi], b[ni][0], b[ni][1]);
    }
}

#define ZERO_ACCH(acc) do { \
    _Pragma("unroll") for (int _a = 0; _a < 4; _a++) \
    _Pragma("unroll") for (int _b = 0; _b < 4; _b++) { \
        acc[_a][_b][0] = 0u; acc[_a][_b][1] = 0u; } } while (0)

// ============================ prep: x -> fp16, weights -> fp16, Z -> 0 ============================
__global__ __launch_bounds__(256) void prep_h(const float4* __restrict__ x,
                                              const float4* __restrict__ theta_w,
                                              const float4* __restrict__ phi_w,
                                              const float4* __restrict__ proj_w,
                                              uint2* __restrict__ xb,
                                              uint2* __restrict__ w2,
                                              float* __restrict__ Z, int n4)
{
    const int gt = blockIdx.x * blockDim.x + threadIdx.x;
    const int stride = gridDim.x * blockDim.x;
    if (gt < NBATCH * SDIM) Z[gt] = 0.0f;
    for (int i = gt; i < n4; i += stride) {
        float4 v = x[i];
        __half2 a = __floats2half2_rn(v.x, v.y);
        __half2 b = __floats2half2_rn(v.z, v.w);
        xb[i] = make_uint2(hbits(a), hbits(b));
    }
    if (gt < 8192) {        // theta_w, phi_w: 128x256 each
        float4 v = theta_w[gt];
        __half2 a = __floats2half2_rn(v.x, v.y);
        __half2 b = __floats2half2_rn(v.z, v.w);
        w2[gt] = make_uint2(hbits(a), hbits(b));
        v = phi_w[gt];
        a = __floats2half2_rn(v.x, v.y);
        b = __floats2half2_rn(v.z, v.w);
        w2[8192 + gt] = make_uint2(hbits(a), hbits(b));
    }
    if (gt < 16384) {       // proj_w: 256x256 -> w2 rows 256-511
        float4 v = proj_w[gt];
        __half2 a = __floats2half2_rn(v.x, v.y);
        __half2 b = __floats2half2_rn(v.z, v.w);
        w2[16384 + gt] = make_uint2(hbits(a), hbits(b));
    }
}

// ============================ projections (HMMA trans-A, f16 acc) ============================
// tp[s][o] = sum_c xb[c,s] * w2[o,c]. theta (o 0-127), phi (128-255), xp^T (256-511).
#define SA2(st) ((uint32_t)((st) * 32768))
#define SB2(st) ((uint32_t)((st) * 32768 + 16384))
__global__ __launch_bounds__(256)
void projections_hmma(const __half* __restrict__ xb,
                      const __half* __restrict__ w2,
                      __half* __restrict__ tp)
{
    extern __shared__ char smem[];
    const uint32_t sb = smem_u32(smem);
    const int tid = threadIdx.x, lane = tid & 31, wid = tid >> 5;
    const int wm = wid & 1, wn = wid >> 1;
    const int z = blockIdx.z, m0 = blockIdx.y * 128, n0 = blockIdx.x * 128;

    const __half* Abase = xb + (size_t)z * CDIM * SDIM + m0;
    const __half* Bbase = w2 + (size_t)n0 * 256;

    uint32_t acc[4][4][2];
    ZERO_ACCH(acc);

    load_tile_64x128(sb + SA2(0), Abase, SDIM);
    load_tileT<128, 256>(sb + SB2(0), Bbase, 256);
    CP_COMMIT();

    const int KT = 4;
    #pragma unroll
    for (int kt = 0; kt < KT; kt++) {
        if (kt + 1 < KT) {
            load_tile_64x128(sb + SA2((kt + 1) & 1), Abase + (size_t)(kt + 1) * 64 * SDIM, SDIM);
            load_tileT<128, 256>(sb + SB2((kt + 1) & 1), Bbase + (kt + 1) * 64, 256);
            CP_COMMIT();
            CP_WAIT(1);
        } else {
            CP_WAIT(0);
        }
        __syncthreads();
        compute_chunk_At(sb + SA2(kt & 1), sb + SB2(kt & 1), wm, wn, lane, acc);
        __syncthreads();
    }

    // epilogue: acc regs ARE packed half2 -> direct stores
    const int lrow = lane >> 2, lcol2 = (lane & 3) * 2;
    #pragma unroll
    for (int mi = 0; mi < 4; mi++) {
        const int gr0 = m0 + wm * 64 + mi * 16 + lrow;   // s
        #pragma unroll
        for (int ni = 0; ni < 4; ni++) {
            const int col = n0 + wn * 32 + ni * 8 + lcol2;  // o in [0,512)
            *reinterpret_cast<uint32_t*>(tp + ((size_t)z * SDIM + gr0) * 512 + col) = acc[mi][ni][0];
            *reinterpret_cast<uint32_t*>(tp + ((size_t)z * SDIM + gr0 + 8) * 512 + col) = acc[mi][ni][1];
        }
    }
}

// ============================ fused logits + exp (f16 acc, ld=512) ============================
__global__ __launch_bounds__(256)
void logits_exp_hmma(const __half* __restrict__ tp,
                     __half* __restrict__ f,
                     float* __restrict__ Z)
{
    extern __shared__ char smem[];
    const uint32_t sb = smem_u32(smem);
    const int tid = threadIdx.x, lane = tid & 31, wid = tid >> 5;
    const int wm = wid & 1, wn = wid >> 1;
    const int z = blockIdx.z, m0 = blockIdx.y * 128, n0 = blockIdx.x * 128;

    const __half* Abase = tp + ((size_t)(z * SDIM + m0)) * 512;        // theta
    const __half* Bbase = tp + ((size_t)(z * SDIM + n0)) * 512 + 128;  // phi

    uint32_t acc[4][4][2];
    ZERO_ACCH(acc);

    load_tileT<128, 256>(sb + SA2(0), Abase, 512);
    load_tileT<128, 256>(sb + SB2(0), Bbase, 512);
    CP_COMMIT();
    load_tileT<128, 256>(sb + SA2(1), Abase + 64, 512);
    load_tileT<128, 256>(sb + SB2(1), Bbase + 64, 512);
    CP_COMMIT();

    CP_WAIT(1);
    __syncthreads();
    compute_chunk(sb + SA2(0), sb + SB2(0), wm * 64, wn * 32, lane, acc);
    CP_WAIT(0);
    __syncthreads();
    compute_chunk(sb + SA2(1), sb + SB2(1), wm * 64, wn * 32, lane, acc);

    const float alpha = 0.08838834764831845f; // 1/sqrt(128)
    const int lrow = lane >> 2, lcol2 = (lane & 3) * 2;
    #pragma unroll
    for (int mi = 0; mi < 4; mi++) {
        const int gr0 = m0 + wm * 64 + mi * 16 + lrow;
        const int gr1 = gr0 + 8;
        float rs0 = 0.0f, rs1 = 0.0f;
        #pragma unroll
        for (int ni = 0; ni < 4; ni++) {
            const int col = n0 + wn * 32 + ni * 8 + lcol2;
            const float2 p0 = h2f(acc[mi][ni][0]);   // row gr0: (col, col+1)
            const float2 p1 = h2f(acc[mi][ni][1]);   // row gr1
            float e00 = __expf(p0.x * alpha);
            float e01 = __expf(p0.y * alpha);
            float e10 = __expf(p1.x * alpha);
            float e11 = __expf(p1.y * alpha);
            rs0 += e00 + e01; rs1 += e10 + e11;
            __half2 h0 = __floats2half2_rn(e00, e01);
            __half2 h1 = __floats2half2_rn(e10, e11);
            *reinterpret_cast<uint32_t*>(f + ((size_t)z * SDIM + gr0) * SDIM + col) = hbits(h0);
            *reinterpret_cast<uint32_t*>(f + ((size_t)z * SDIM + gr1) * SDIM + col) = hbits(h1);
        }
        rs0 += __shfl_xor_sync(0xffffffffu, rs0, 1);
        rs0 += __shfl_xor_sync(0xffffffffu, rs0, 2);
        rs1 += __shfl_xor_sync(0xffffffffu, rs1, 1);
        rs1 += __shfl_xor_sync(0xffffffffu, rs1, 2);
        if ((lane & 3) == 0) {
            atomicAdd(&Z[(size_t)z * SDIM + gr0], rs0);
            atomicAdd(&Z[(size_t)z * SDIM + gr1], rs1);
        }
    }
}

// ============================ fused attend+proj (trans-A, f16 acc, 3-stage) ============================
// out[n][o][s] = x[n][o][s] + (1/Z[s]) * sum_t xp[o,t] * f[s,t]
#define ASA(st) ((uint32_t)((st) * 32768))
#define ASB(st) ((uint32_t)((st) * 32768 + 16384))
__global__ __launch_bounds__(256)
void attend_proj_hmma(const __half* __restrict__ tp,
                      const __half* __restrict__ f,
                      const float* __restrict__ Z,
                      const float* __restrict__ x,
                      float* __restrict__ out)
{
    extern __shared__ char smem[];
    const uint32_t sb = smem_u32(smem);
    const int tid = threadIdx.x, lane = tid & 31, wid = tid >> 5;
    const int wm = wid & 1, wn = wid >> 1;
    const int z = blockIdx.z, m0 = blockIdx.y * 128, n0 = blockIdx.x * 128;

    const __half* Abase = tp + (size_t)z * SDIM * 512 + 256 + m0;   // rows t, ld 512
    const __half* Bbase = f + ((size_t)z * SDIM + n0) * SDIM;       // rows s, ld SDIM

    uint32_t acc[4][4][2];
    ZERO_ACCH(acc);

    load_tile_64x128(sb + ASA(0), Abase, 512);
    load_tileT<128, 256>(sb + ASB(0), Bbase, SDIM);
    CP_COMMIT();
    load_tile_64x128(sb + ASA(1), Abase + (size_t)64 * 512, 512);
    load_tileT<128, 256>(sb + ASB(1), Bbase + 64, SDIM);
    CP_COMMIT();

    const int KT = SDIM / 64; // 64
    for (int kt = 0; kt < KT; kt++) {
        if (kt + 1 < KT) { CP_WAIT(1); } else { CP_WAIT(0); }
        __syncthreads();
        if (kt + 2 < KT) {
            const int st = (kt + 2) % 3;
            load_tile_64x128(sb + ASA(st), Abase + (size_t)(kt + 2) * 64 * 512, 512);
            load_tileT<128, 256>(sb + ASB(st), Bbase + (kt + 2) * 64, SDIM);
            CP_COMMIT();
        }
        compute_chunk_At(sb + ASA(kt % 3), sb + ASB(kt % 3), wm, wn, lane, acc);
    }

    // epilogue: rows = o, cols = s; scale by 1/Z[s], add residual x, fp32 out
    const int lrow = lane >> 2, lcol2 = (lane & 3) * 2;
    #pragma unroll
    for (int ni = 0; ni < 4; ni++) {
        const int col = n0 + wn * 32 + ni * 8 + lcol2;   // s (even)
        const float2 zc = *reinterpret_cast<const float2*>(&Z[(size_t)z * SDIM + col]);
        const float izx = 1.0f / zc.x, izy = 1.0f / zc.y;
        #pragma unroll
        for (int mi = 0; mi < 4; mi++) {
            const int gr0 = m0 + wm * 64 + mi * 16 + lrow;   // o
            const int gr1 = gr0 + 8;
            const float2 a0 = h2f(acc[mi][ni][0]);   // row gr0: (col, col+1)
            const float2 a1 = h2f(acc[mi][ni][1]);   // row gr1
            const float2 x0 = *reinterpret_cast<const float2*>(x + ((size_t)z * CDIM + gr0) * SDIM + col);
            const float2 x1 = *reinterpret_cast<const float2*>(x + ((size_t)z * CDIM + gr1) * SDIM + col);
            float2 v0 = make_float2(a0.x * izx + x0.x, a0.y * izy + x0.y);
            float2 v1 = make_float2(a1.x * izx + x1.x, a1.y * izy + x1.y);
            *reinterpret_cast<float2*>(out + ((size_t)z * CDIM + gr0) * SDIM + col) = v0;
            *reinterpret_cast<float2*>(out + ((size_t)z * CDIM + gr1) * SDIM + col) = v1;
        }
    }
}

// ============================ launch ============================
extern "C" void kernel_launch(void* const* d_in, const int* in_sizes, int n_in,
                              void* d_out, int out_size)
{
    const float* x       = (const float*)d_in[0];
    const float* theta_w = (const float*)d_in[1];
    const float* phi_w   = (const float*)d_in[2];
    const float* proj_w  = (const float*)d_in[3];
    float* out = (float*)d_out;

    __half *tp, *f, *xb, *w2;
    float *Z;
    cudaGetSymbolAddress((void**)&tp, g_tp);
    cudaGetSymbolAddress((void**)&f,  g_f);
    cudaGetSymbolAddress((void**)&xb, g_xb);
    cudaGetSymbolAddress((void**)&w2, g_w2);
    cudaGetSymbolAddress((void**)&Z,  g_Z);

    cudaFuncSetAttribute(projections_hmma, cudaFuncAttributeMaxDynamicSharedMemorySize, 65536);
    cudaFuncSetAttribute(logits_exp_hmma,  cudaFuncAttributeMaxDynamicSharedMemorySize, 65536);
    cudaFuncSetAttribute(attend_proj_hmma, cudaFuncAttributeMaxDynamicSharedMemorySize, 98304);

    // 0: fp16 conversions + Z zero
    prep_h<<<1024, 256>>>((const float4*)x, (const float4*)theta_w, (const float4*)phi_w,
                          (const float4*)proj_w, (uint2*)xb, (uint2*)w2, Z,
                          (int)((size_t)NBATCH * CDIM * SDIM / 4));

    // 1: all three projections (theta, phi, xp = proj_w @ x) in one GEMM
    projections_hmma<<<dim3(4, 32, 4), 256, 65536>>>(xb, w2, tp);

    // 2: fused logits -> exp + row sums
    logits_exp_hmma<<<dim3(32, 32, 4), 256, 65536>>>(tp, f, Z);

    // 3: fused attend + projection + residual + 1/Z
    attend_proj_hmma<<<dim3(32, 2, 4), 256, 98304>>>(tp, f, Z, x, out);
}

// round 14
// speedup vs baseline: 1.0587x; 1.0092x over previous
#include <cuda_runtime.h>
#include <cuda_fp16.h>
#include <math.h>
#include <cstdint>

#define SDIM 4096
#define CDIM 256
#define EDIM 128
#define NBATCH 4

// ---- scratch (device globals: allocation-free) ----
// tp rows = spatial s/t, 512 cols: [0:128)=theta, [128:256)=phi, [256:512)=xp^T (= (proj_w@x)[o,t])
__device__ __half g_tp[(size_t)NBATCH * SDIM * 512];
__device__ __half g_f [(size_t)NBATCH * SDIM * SDIM];       // unnormalized exp(logits)
__device__ __half g_xb[(size_t)NBATCH * CDIM * SDIM];       // x fp16 [n][c][s]
__device__ __half g_w2[512 * 256];                          // rows: 0-127 theta_w, 128-255 phi_w, 256-511 proj_w
__device__ float  g_Z [(size_t)NBATCH * SDIM];              // row sums

// ============================ low-level helpers ============================
__device__ __forceinline__ uint32_t smem_u32(const void* p) {
    uint32_t a;
    asm("{ .reg .u64 t; cvta.to.shared.u64 t, %1; cvt.u32.u64 %0, t; }" : "=r"(a) : "l"(p));
    return a;
}
__device__ __forceinline__ void ldsm4(uint32_t r[4], uint32_t addr) {
    asm volatile("ldmatrix.sync.aligned.m8n8.x4.shared.b16 {%0,%1,%2,%3}, [%4];"
                 : "=r"(r[0]), "=r"(r[1]), "=r"(r[2]), "=r"(r[3]) : "r"(addr));
}
__device__ __forceinline__ void ldsm4t(uint32_t r[4], uint32_t addr) {
    asm volatile("ldmatrix.sync.aligned.m8n8.x4.trans.shared.b16 {%0,%1,%2,%3}, [%4];"
                 : "=r"(r[0]), "=r"(r[1]), "=r"(r[2]), "=r"(r[3]) : "r"(addr));
}
// f16-accumulate HMMA: D(2 regs of f16x2) = A*B + D
__device__ __forceinline__ void mma16816h(uint32_t c[2], const uint32_t a[4], uint32_t b0, uint32_t b1) {
    asm volatile("mma.sync.aligned.m16n8k16.row.col.f16.f16.f16.f16 "
                 "{%0,%1},{%2,%3,%4,%5},{%6,%7},{%0,%1};"
                 : "+r"(c[0]), "+r"(c[1])
                 : "r"(a[0]), "r"(a[1]), "r"(a[2]), "r"(a[3]), "r"(b0), "r"(b1));
}
__device__ __forceinline__ void cp16(uint32_t saddr, const void* g) {
    asm volatile("cp.async.cg.shared.global [%0], [%1], 16;" :: "r"(saddr), "l"(g));
}
#define CP_COMMIT() asm volatile("cp.async.commit_group;" ::: "memory")
#define CP_WAIT(N)  asm volatile("cp.async.wait_group %0;" :: "n"(N) : "memory")

__device__ __forceinline__ uint32_t hbits(__half2 h) { return *reinterpret_cast<uint32_t*>(&h); }
__device__ __forceinline__ float2 h2f(uint32_t v) {
    __half2 h = *reinterpret_cast<__half2*>(&v);
    return __half22float2(h);
}

// R rows x 64 cols f16 (128B rows), XOR-16B swizzle keyed on row&7. NT threads.
template<int R, int NT>
__device__ __forceinline__ void load_tileT(uint32_t sdst, const __half* g, int ldg) {
    const int tid = threadIdx.x;
    #pragma unroll
    for (int i = 0; i < (R * 8) / NT; i++) {
        const int c = tid + i * NT;
        const int r = c >> 3, kc = c & 7;
        const uint32_t so = sdst + r * 128 + (((uint32_t)kc * 16) ^ ((r & 7) * 16));
        cp16(so, g + (size_t)r * ldg + kc * 8);
    }
}
// 64 rows x 128 cols f16 (256B rows), 256 threads (trans-A operand tile).
__device__ __forceinline__ void load_tile_64x128(uint32_t sdst, const __half* g, int ldg) {
    const int tid = threadIdx.x;
    #pragma unroll
    for (int i = 0; i < 4; i++) {
        const int c = tid + i * 256;
        const int r = c >> 4, kc = c & 15;
        const uint32_t so = sdst + r * 256 + (((uint32_t)kc * 16) ^ ((r & 7) * 16));
        cp16(so, g + (size_t)r * ldg + kc * 8);
    }
}

// ---- 64x32 warp-tile chunk (regular A), f16 accumulate ----
__device__ __forceinline__ void compute_chunk(uint32_t sA, uint32_t sB,
                                              int m_base, int n_base, int lane,
                                              uint32_t acc[4][4][2]) {
    #pragma unroll
    for (int ks = 0; ks < 4; ks++) {
        const int kc = ks * 2 + (lane >> 4);
        uint32_t a[4][4];
        #pragma unroll
        for (int mi = 0; mi < 4; mi++) {
            const int row = m_base + mi * 16 + (lane & 15);
            ldsm4(a[mi], sA + row * 128 + (((uint32_t)kc * 16) ^ ((row & 7) * 16)));
        }
        uint32_t b[4][2];
        #pragma unroll
        for (int nh = 0; nh < 2; nh++) {
            const int row = n_base + nh * 16 + (lane & 15);
            uint32_t r4[4];
            ldsm4(r4, sB + row * 128 + (((uint32_t)kc * 16) ^ ((row & 7) * 16)));
            b[nh * 2 + 0][0] = r4[0]; b[nh * 2 + 0][1] = r4[2];
            b[nh * 2 + 1][0] = r4[1]; b[nh * 2 + 1][1] = r4[3];
        }
        #pragma unroll
        for (int mi = 0; mi < 4; mi++)
            #pragma unroll
            for (int ni = 0; ni < 4; ni++)
                mma16816h(acc[mi][ni], a[mi], b[ni][0], b[ni][1]);
    }
}

// ---- trans-A chunk: A stored [k][m] (64 rows x 128 cols, 256B rows), B regular [n][k] ----
__device__ __forceinline__ void compute_chunk_At(uint32_t sA, uint32_t sB,
                                                 int wm, int wn, int lane,
                                                 uint32_t acc[4][4][2]) {
    #pragma unroll
    for (int ks = 0; ks < 4; ks++) {
        uint32_t a[4][4];
        const int crow_l = ks * 16 + (lane & 7) + ((lane >> 4) & 1) * 8;
        #pragma unroll
        for (int mi = 0; mi < 4; mi++) {
            const int scol = wm * 64 + mi * 16 + ((lane >> 3) & 1) * 8;
            ldsm4t(a[mi], sA + crow_l * 256 + ((((uint32_t)scol >> 3) * 16) ^ ((crow_l & 7) * 16)));
        }
        const int kc = ks * 2 + (lane >> 4);
        uint32_t b[4][2];
        #pragma unroll
        for (int nh = 0; nh < 2; nh++) {
            const int row = wn * 32 + nh * 16 + (lane & 15);
            uint32_t r4[4];
            ldsm4(r4, sB + row * 128 + (((uint32_t)kc * 16) ^ ((row & 7) * 16)));
            b[nh * 2 + 0][0] = r4[0]; b[nh * 2 + 0][1] = r4[2];
            b[nh * 2 + 1][0] = r4[1]; b[nh * 2 + 1][1] = r4[3];
        }
        #pragma unroll
        for (int mi = 0; mi < 4; mi++)
            #pragma unroll
            for (int ni = 0; ni < 4; ni++)
                mma16816h(acc[mi][ni], a[mi], b[ni][0], b[ni][1]);
    }
}

#define ZERO_ACCH(acc) do { \
    _Pragma("unroll") for (int _a = 0; _a < 4; _a++) \
    _Pragma("unroll") for (int _b = 0; _b < 4; _b++) { \
        acc[_a][_b][0] = 0u; acc[_a][_b][1] = 0u; } } while (0)

// ============================ prep: x -> fp16, weights -> fp16, Z -> 0 ============================
__global__ __launch_bounds__(256) void prep_h(const float4* __restrict__ x,
                                              const float4* __restrict__ theta_w,
                                              const float4* __restrict__ phi_w,
                                              const float4* __restrict__ proj_w,
                                              uint2* __restrict__ xb,
                                              uint2* __restrict__ w2,
                                              float* __restrict__ Z, int n4)
{
    const int gt = blockIdx.x * blockDim.x + threadIdx.x;
    const int stride = gridDim.x * blockDim.x;
    if (gt < NBATCH * SDIM) Z[gt] = 0.0f;
    for (int i = gt; i < n4; i += stride) {
        float4 v = x[i];
        __half2 a = __floats2half2_rn(v.x, v.y);
        __half2 b = __floats2half2_rn(v.z, v.w);
        xb[i] = make_uint2(hbits(a), hbits(b));
    }
    if (gt < 8192) {        // theta_w, phi_w: 128x256 each
        float4 v = theta_w[gt];
        __half2 a = __floats2half2_rn(v.x, v.y);
        __half2 b = __floats2half2_rn(v.z, v.w);
        w2[gt] = make_uint2(hbits(a), hbits(b));
        v = phi_w[gt];
        a = __floats2half2_rn(v.x, v.y);
        b = __floats2half2_rn(v.z, v.w);
        w2[8192 + gt] = make_uint2(hbits(a), hbits(b));
    }
    if (gt < 16384) {       // proj_w: 256x256 -> w2 rows 256-511
        float4 v = proj_w[gt];
        __half2 a = __floats2half2_rn(v.x, v.y);
        __half2 b = __floats2half2_rn(v.z, v.w);
        w2[16384 + gt] = make_uint2(hbits(a), hbits(b));
    }
}

// ============================ shared projection body (HMMA trans-A, f16 acc) ============================
// tp[s][o-tile] = sum_c xb[c,s] * w2[o,c] for o in [n0, n0+128)
#define SA2(st) ((uint32_t)((st) * 32768))
#define SB2(st) ((uint32_t)((st) * 32768 + 16384))
__device__ __forceinline__ void projection_body(uint32_t sb,
                                                const __half* __restrict__ xb,
                                                const __half* __restrict__ w2,
                                                __half* tp,
                                                int z, int m0, int n0)
{
    const int tid = threadIdx.x, lane = tid & 31, wid = tid >> 5;
    const int wm = wid & 1, wn = wid >> 1;

    const __half* Abase = xb + (size_t)z * CDIM * SDIM + m0;
    const __half* Bbase = w2 + (size_t)n0 * 256;

    uint32_t acc[4][4][2];
    ZERO_ACCH(acc);

    load_tile_64x128(sb + SA2(0), Abase, SDIM);
    load_tileT<128, 256>(sb + SB2(0), Bbase, 256);
    CP_COMMIT();

    const int KT = 4;
    #pragma unroll
    for (int kt = 0; kt < KT; kt++) {
        if (kt + 1 < KT) {
            load_tile_64x128(sb + SA2((kt + 1) & 1), Abase + (size_t)(kt + 1) * 64 * SDIM, SDIM);
            load_tileT<128, 256>(sb + SB2((kt + 1) & 1), Bbase + (kt + 1) * 64, 256);
            CP_COMMIT();
            CP_WAIT(1);
        } else {
            CP_WAIT(0);
        }
        __syncthreads();
        compute_chunk_At(sb + SA2(kt & 1), sb + SB2(kt & 1), wm, wn, lane, acc);
        __syncthreads();
    }

    // epilogue: acc regs ARE packed half2 -> direct stores
    const int lrow = lane >> 2, lcol2 = (lane & 3) * 2;
    #pragma unroll
    for (int mi = 0; mi < 4; mi++) {
        const int gr0 = m0 + wm * 64 + mi * 16 + lrow;   // s
        #pragma unroll
        for (int ni = 0; ni < 4; ni++) {
            const int col = n0 + wn * 32 + ni * 8 + lcol2;  // o in [0,512)
            *reinterpret_cast<uint32_t*>(tp + ((size_t)z * SDIM + gr0) * 512 + col) = acc[mi][ni][0];
            *reinterpret_cast<uint32_t*>(tp + ((size_t)z * SDIM + gr0 + 8) * 512 + col) = acc[mi][ni][1];
        }
    }
}

// ============================ projections (theta/phi only): grid (2, 32, 4) ============================
__global__ __launch_bounds__(256)
void projections_hmma(const __half* __restrict__ xb,
                      const __half* __restrict__ w2,
                      __half* __restrict__ tp)
{
    extern __shared__ char smem[];
    projection_body(smem_u32(smem), xb, w2, tp,
                    blockIdx.z, blockIdx.y * 128, blockIdx.x * 128);
}

// ============================ fused logits+exp AND xp-projection: grid (34, 32, 4) ============================
// bx < 32: logits for n-tile bx.  bx in {32,33}: xp-projection for o-tile 256 + (bx-32)*128.
__global__ __launch_bounds__(256)
void logits_xp_hmma(__half* tp,
                    __half* __restrict__ f,
                    float* __restrict__ Z,
                    const __half* __restrict__ xb,
                    const __half* __restrict__ w2)
{
    extern __shared__ char smem[];
    const uint32_t sb = smem_u32(smem);
    const int z = blockIdx.z, m0 = blockIdx.y * 128;

    if (blockIdx.x >= 32) {
        // xp projection path: writes tp[:, 256:512) — disjoint from logits' reads (tp[:, 0:256))
        projection_body(sb, xb, w2, tp, z, m0, 256 + (blockIdx.x - 32) * 128);
        return;
    }

    // ---- logits path (R13-proven) ----
    const int tid = threadIdx.x, lane = tid & 31, wid = tid >> 5;
    const int wm = wid & 1, wn = wid >> 1;
    const int n0 = blockIdx.x * 128;

    const __half* Abase = tp + ((size_t)(z * SDIM + m0)) * 512;        // theta
    const __half* Bbase = tp + ((size_t)(z * SDIM + n0)) * 512 + 128;  // phi

    uint32_t acc[4][4][2];
    ZERO_ACCH(acc);

    load_tileT<128, 256>(sb + SA2(0), Abase, 512);
    load_tileT<128, 256>(sb + SB2(0), Bbase, 512);
    CP_COMMIT();
    load_tileT<128, 256>(sb + SA2(1), Abase + 64, 512);
    load_tileT<128, 256>(sb + SB2(1), Bbase + 64, 512);
    CP_COMMIT();

    CP_WAIT(1);
    __syncthreads();
    compute_chunk(sb + SA2(0), sb + SB2(0), wm * 64, wn * 32, lane, acc);
    CP_WAIT(0);
    __syncthreads();
    compute_chunk(sb + SA2(1), sb + SB2(1), wm * 64, wn * 32, lane, acc);

    const float alpha = 0.08838834764831845f; // 1/sqrt(128)
    const int lrow = lane >> 2, lcol2 = (lane & 3) * 2;
    #pragma unroll
    for (int mi = 0; mi < 4; mi++) {
        const int gr0 = m0 + wm * 64 + mi * 16 + lrow;
        const int gr1 = gr0 + 8;
        float rs0 = 0.0f, rs1 = 0.0f;
        #pragma unroll
        for (int ni = 0; ni < 4; ni++) {
            const int col = n0 + wn * 32 + ni * 8 + lcol2;
            const float2 p0 = h2f(acc[mi][ni][0]);   // row gr0: (col, col+1)
            const float2 p1 = h2f(acc[mi][ni][1]);   // row gr1
            float e00 = __expf(p0.x * alpha);
            float e01 = __expf(p0.y * alpha);
            float e10 = __expf(p1.x * alpha);
            float e11 = __expf(p1.y * alpha);
            rs0 += e00 + e01; rs1 += e10 + e11;
            __half2 h0 = __floats2half2_rn(e00, e01);
            __half2 h1 = __floats2half2_rn(e10, e11);
            *reinterpret_cast<uint32_t*>(f + ((size_t)z * SDIM + gr0) * SDIM + col) = hbits(h0);
            *reinterpret_cast<uint32_t*>(f + ((size_t)z * SDIM + gr1) * SDIM + col) = hbits(h1);
        }
        rs0 += __shfl_xor_sync(0xffffffffu, rs0, 1);
        rs0 += __shfl_xor_sync(0xffffffffu, rs0, 2);
        rs1 += __shfl_xor_sync(0xffffffffu, rs1, 1);
        rs1 += __shfl_xor_sync(0xffffffffu, rs1, 2);
        if ((lane & 3) == 0) {
            atomicAdd(&Z[(size_t)z * SDIM + gr0], rs0);
            atomicAdd(&Z[(size_t)z * SDIM + gr1], rs1);
        }
    }
}

// ============================ fused attend+proj (R13-proven, trans-A, f16 acc, 3-stage) ============================
// out[n][o][s] = x[n][o][s] + (1/Z[s]) * sum_t xp[o,t] * f[s,t]
#define ASA(st) ((uint32_t)((st) * 32768))
#define ASB(st) ((uint32_t)((st) * 32768 + 16384))
__global__ __launch_bounds__(256)
void attend_proj_hmma(const __half* __restrict__ tp,
                      const __half* __restrict__ f,
                      const float* __restrict__ Z,
                      const float* __restrict__ x,
                      float* __restrict__ out)
{
    extern __shared__ char smem[];
    const uint32_t sb = smem_u32(smem);
    const int tid = threadIdx.x, lane = tid & 31, wid = tid >> 5;
    const int wm = wid & 1, wn = wid >> 1;
    const int z = blockIdx.z, m0 = blockIdx.y * 128, n0 = blockIdx.x * 128;

    const __half* Abase = tp + (size_t)z * SDIM * 512 + 256 + m0;   // rows t, ld 512
    const __half* Bbase = f + ((size_t)z * SDIM + n0) * SDIM;       // rows s, ld SDIM

    uint32_t acc[4][4][2];
    ZERO_ACCH(acc);

    load_tile_64x128(sb + ASA(0), Abase, 512);
    load_tileT<128, 256>(sb + ASB(0), Bbase, SDIM);
    CP_COMMIT();
    load_tile_64x128(sb + ASA(1), Abase + (size_t)64 * 512, 512);
    load_tileT<128, 256>(sb + ASB(1), Bbase + 64, SDIM);
    CP_COMMIT();

    const int KT = SDIM / 64; // 64
    for (int kt = 0; kt < KT; kt++) {
        if (kt + 1 < KT) { CP_WAIT(1); } else { CP_WAIT(0); }
        __syncthreads();
        if (kt + 2 < KT) {
            const int st = (kt + 2) % 3;
            load_tile_64x128(sb + ASA(st), Abase + (size_t)(kt + 2) * 64 * 512, 512);
            load_tileT<128, 256>(sb + ASB(st), Bbase + (kt + 2) * 64, SDIM);
            CP_COMMIT();
        }
        compute_chunk_At(sb + ASA(kt % 3), sb + ASB(kt % 3), wm, wn, lane, acc);
    }

    // epilogue: rows = o, cols = s; scale by 1/Z[s], add residual x, fp32 out
    const int lrow = lane >> 2, lcol2 = (lane & 3) * 2;
    #pragma unroll
    for (int ni = 0; ni < 4; ni++) {
        const int col = n0 + wn * 32 + ni * 8 + lcol2;   // s (even)
        const float2 zc = *reinterpret_cast<const float2*>(&Z[(size_t)z * SDIM + col]);
        const float izx = 1.0f / zc.x, izy = 1.0f / zc.y;
        #pragma unroll
        for (int mi = 0; mi < 4; mi++) {
            const int gr0 = m0 + wm * 64 + mi * 16 + lrow;   // o
            const int gr1 = gr0 + 8;
            const float2 a0 = h2f(acc[mi][ni][0]);   // row gr0: (col, col+1)
            const float2 a1 = h2f(acc[mi][ni][1]);   // row gr1
            const float2 x0 = *reinterpret_cast<const float2*>(x + ((size_t)z * CDIM + gr0) * SDIM + col);
            const float2 x1 = *reinterpret_cast<const float2*>(x + ((size_t)z * CDIM + gr1) * SDIM + col);
            float2 v0 = make_float2(a0.x * izx + x0.x, a0.y * izy + x0.y);
            float2 v1 = make_float2(a1.x * izx + x1.x, a1.y * izy + x1.y);
            *reinterpret_cast<float2*>(out + ((size_t)z * CDIM + gr0) * SDIM + col) = v0;
            *reinterpret_cast<float2*>(out + ((size_t)z * CDIM + gr1) * SDIM + col) = v1;
        }
    }
}

// ============================ launch ============================
extern "C" void kernel_launch(void* const* d_in, const int* in_sizes, int n_in,
                              void* d_out, int out_size)
{
    const float* x       = (const float*)d_in[0];
    const float* theta_w = (const float*)d_in[1];
    const float* phi_w   = (const float*)d_in[2];
    const float* proj_w  = (const float*)d_in[3];
    float* out = (float*)d_out;

    __half *tp, *f, *xb, *w2;
    float *Z;
    cudaGetSymbolAddress((void**)&tp, g_tp);
    cudaGetSymbolAddress((void**)&f,  g_f);
    cudaGetSymbolAddress((void**)&xb, g_xb);
    cudaGetSymbolAddress((void**)&w2, g_w2);
    cudaGetSymbolAddress((void**)&Z,  g_Z);

    cudaFuncSetAttribute(projections_hmma, cudaFuncAttributeMaxDynamicSharedMemorySize, 65536);
    cudaFuncSetAttribute(logits_xp_hmma,   cudaFuncAttributeMaxDynamicSharedMemorySize, 65536);
    cudaFuncSetAttribute(attend_proj_hmma, cudaFuncAttributeMaxDynamicSharedMemorySize, 98304);

    // 0: fp16 conversions + Z zero
    prep_h<<<1024, 256>>>((const float4*)x, (const float4*)theta_w, (const float4*)phi_w,
                          (const float4*)proj_w, (uint2*)xb, (uint2*)w2, Z,
                          (int)((size_t)NBATCH * CDIM * SDIM / 4));

    // 1: theta + phi projections only (o-tiles 0,1)
    projections_hmma<<<dim3(2, 32, 4), 256, 65536>>>(xb, w2, tp);

    // 2: fused logits->exp + xp-projection in ONE launch (xp CTAs overlap logits)
    logits_xp_hmma<<<dim3(34, 32, 4), 256, 65536>>>(tp, f, Z, xb, w2);

    // 3: fused attend + projection + residual + 1/Z
    attend_proj_hmma<<<dim3(32, 2, 4), 256, 98304>>>(tp, f, Z, x, out);
}

// round 15
// speedup vs baseline: 1.0592x; 1.0004x over previous
#include <cuda_runtime.h>
#include <cuda_fp16.h>
#include <math.h>
#include <cstdint>

#define SDIM 4096
#define CDIM 256
#define EDIM 128
#define NBATCH 4

// ---- scratch (device globals: allocation-free) ----
// tp rows = spatial s/t, 512 cols: [0:128)=theta, [128:256)=phi, [256:512)=xp^T (= (proj_w@x)[o,t])
__device__ __half g_tp[(size_t)NBATCH * SDIM * 512];
__device__ __half g_f [(size_t)NBATCH * SDIM * SDIM];       // unnormalized exp(logits)
__device__ __half g_xb[(size_t)NBATCH * CDIM * SDIM];       // x fp16 [n][c][s]
__device__ __half g_w2[512 * 256];                          // rows: 0-127 theta_w, 128-255 phi_w, 256-511 proj_w
__device__ float  g_Z [(size_t)NBATCH * SDIM];              // row sums

// ============================ low-level helpers ============================
__device__ __forceinline__ uint32_t smem_u32(const void* p) {
    uint32_t a;
    asm("{ .reg .u64 t; cvta.to.shared.u64 t, %1; cvt.u32.u64 %0, t; }" : "=r"(a) : "l"(p));
    return a;
}
__device__ __forceinline__ void ldsm4(uint32_t r[4], uint32_t addr) {
    asm volatile("ldmatrix.sync.aligned.m8n8.x4.shared.b16 {%0,%1,%2,%3}, [%4];"
                 : "=r"(r[0]), "=r"(r[1]), "=r"(r[2]), "=r"(r[3]) : "r"(addr));
}
__device__ __forceinline__ void ldsm4t(uint32_t r[4], uint32_t addr) {
    asm volatile("ldmatrix.sync.aligned.m8n8.x4.trans.shared.b16 {%0,%1,%2,%3}, [%4];"
                 : "=r"(r[0]), "=r"(r[1]), "=r"(r[2]), "=r"(r[3]) : "r"(addr));
}
// f16-accumulate HMMA: D(2 regs of f16x2) = A*B + D
__device__ __forceinline__ void mma16816h(uint32_t c[2], const uint32_t a[4], uint32_t b0, uint32_t b1) {
    asm volatile("mma.sync.aligned.m16n8k16.row.col.f16.f16.f16.f16 "
                 "{%0,%1},{%2,%3,%4,%5},{%6,%7},{%0,%1};"
                 : "+r"(c[0]), "+r"(c[1])
                 : "r"(a[0]), "r"(a[1]), "r"(a[2]), "r"(a[3]), "r"(b0), "r"(b1));
}
__device__ __forceinline__ void cp16(uint32_t saddr, const void* g) {
    asm volatile("cp.async.cg.shared.global [%0], [%1], 16;" :: "r"(saddr), "l"(g));
}
#define CP_COMMIT() asm volatile("cp.async.commit_group;" ::: "memory")
#define CP_WAIT(N)  asm volatile("cp.async.wait_group %0;" :: "n"(N) : "memory")

__device__ __forceinline__ uint32_t hbits(__half2 h) { return *reinterpret_cast<uint32_t*>(&h); }
__device__ __forceinline__ float2 h2f(uint32_t v) {
    __half2 h = *reinterpret_cast<__half2*>(&v);
    return __half22float2(h);
}

// R rows x 64 cols f16 (128B rows), XOR-16B swizzle keyed on row&7. NT threads.
template<int R, int NT>
__device__ __forceinline__ void load_tileT(uint32_t sdst, const __half* g, int ldg) {
    const int tid = threadIdx.x;
    #pragma unroll
    for (int i = 0; i < (R * 8) / NT; i++) {
        const int c = tid + i * NT;
        const int r = c >> 3, kc = c & 7;
        const uint32_t so = sdst + r * 128 + (((uint32_t)kc * 16) ^ ((r & 7) * 16));
        cp16(so, g + (size_t)r * ldg + kc * 8);
    }
}
// 64 rows x 128 cols f16 (256B rows), 256 threads (trans-A operand tile).
__device__ __forceinline__ void load_tile_64x128(uint32_t sdst, const __half* g, int ldg) {
    const int tid = threadIdx.x;
    #pragma unroll
    for (int i = 0; i < 4; i++) {
        const int c = tid + i * 256;
        const int r = c >> 4, kc = c & 15;
        const uint32_t so = sdst + r * 256 + (((uint32_t)kc * 16) ^ ((r & 7) * 16));
        cp16(so, g + (size_t)r * ldg + kc * 8);
    }
}

// ---- 64x32 warp-tile chunk (regular A), f16 accumulate ----
__device__ __forceinline__ void compute_chunk(uint32_t sA, uint32_t sB,
                                              int m_base, int n_base, int lane,
                                              uint32_t acc[4][4][2]) {
    #pragma unroll
    for (int ks = 0; ks < 4; ks++) {
        const int kc = ks * 2 + (lane >> 4);
        uint32_t a[4][4];
        #pragma unroll
        for (int mi = 0; mi < 4; mi++) {
            const int row = m_base + mi * 16 + (lane & 15);
            ldsm4(a[mi], sA + row * 128 + (((uint32_t)kc * 16) ^ ((row & 7) * 16)));
        }
        uint32_t b[4][2];
        #pragma unroll
        for (int nh = 0; nh < 2; nh++) {
            const int row = n_base + nh * 16 + (lane & 15);
            uint32_t r4[4];
            ldsm4(r4, sB + row * 128 + (((uint32_t)kc * 16) ^ ((row & 7) * 16)));
            b[nh * 2 + 0][0] = r4[0]; b[nh * 2 + 0][1] = r4[2];
            b[nh * 2 + 1][0] = r4[1]; b[nh * 2 + 1][1] = r4[3];
        }
        #pragma unroll
        for (int mi = 0; mi < 4; mi++)
            #pragma unroll
            for (int ni = 0; ni < 4; ni++)
                mma16816h(acc[mi][ni], a[mi], b[ni][0], b[ni][1]);
    }
}

// ---- trans-A chunk: A stored [k][m] (64 rows x 128 cols, 256B rows), B regular [n][k] ----
__device__ __forceinline__ void compute_chunk_At(uint32_t sA, uint32_t sB,
                                                 int wm, int wn, int lane,
                                                 uint32_t acc[4][4][2]) {
    #pragma unroll
    for (int ks = 0; ks < 4; ks++) {
        uint32_t a[4][4];
        const int crow_l = ks * 16 + (lane & 7) + ((lane >> 4) & 1) * 8;
        #pragma unroll
        for (int mi = 0; mi < 4; mi++) {
            const int scol = wm * 64 + mi * 16 + ((lane >> 3) & 1) * 8;
            ldsm4t(a[mi], sA + crow_l * 256 + ((((uint32_t)scol >> 3) * 16) ^ ((crow_l & 7) * 16)));
        }
        const int kc = ks * 2 + (lane >> 4);
        uint32_t b[4][2];
        #pragma unroll
        for (int nh = 0; nh < 2; nh++) {
            const int row = wn * 32 + nh * 16 + (lane & 15);
            uint32_t r4[4];
            ldsm4(r4, sB + row * 128 + (((uint32_t)kc * 16) ^ ((row & 7) * 16)));
            b[nh * 2 + 0][0] = r4[0]; b[nh * 2 + 0][1] = r4[2];
            b[nh * 2 + 1][0] = r4[1]; b[nh * 2 + 1][1] = r4[3];
        }
        #pragma unroll
        for (int mi = 0; mi < 4; mi++)
            #pragma unroll
            for (int ni = 0; ni < 4; ni++)
                mma16816h(acc[mi][ni], a[mi], b[ni][0], b[ni][1]);
    }
}

#define ZERO_ACCH(acc) do { \
    _Pragma("unroll") for (int _a = 0; _a < 4; _a++) \
    _Pragma("unroll") for (int _b = 0; _b < 4; _b++) { \
        acc[_a][_b][0] = 0u; acc[_a][_b][1] = 0u; } } while (0)

// ============================ prep: x -> fp16, weights -> fp16, Z -> 0 ============================
__global__ __launch_bounds__(256) void prep_h(const float4* __restrict__ x,
                                              const float4* __restrict__ theta_w,
                                              const float4* __restrict__ phi_w,
                                              const float4* __restrict__ proj_w,
                                              uint2* __restrict__ xb,
                                              uint2* __restrict__ w2,
                                              float* __restrict__ Z, int n4)
{
    const int gt = blockIdx.x * blockDim.x + threadIdx.x;
    const int stride = gridDim.x * blockDim.x;
    if (gt < NBATCH * SDIM) Z[gt] = 0.0f;
    for (int i = gt; i < n4; i += stride) {
        float4 v = x[i];
        __half2 a = __floats2half2_rn(v.x, v.y);
        __half2 b = __floats2half2_rn(v.z, v.w);
        xb[i] = make_uint2(hbits(a), hbits(b));
    }
    if (gt < 8192) {        // theta_w, phi_w: 128x256 each
        float4 v = theta_w[gt];
        __half2 a = __floats2half2_rn(v.x, v.y);
        __half2 b = __floats2half2_rn(v.z, v.w);
        w2[gt] = make_uint2(hbits(a), hbits(b));
        v = phi_w[gt];
        a = __floats2half2_rn(v.x, v.y);
        b = __floats2half2_rn(v.z, v.w);
        w2[8192 + gt] = make_uint2(hbits(a), hbits(b));
    }
    if (gt < 16384) {       // proj_w: 256x256 -> w2 rows 256-511
        float4 v = proj_w[gt];
        __half2 a = __floats2half2_rn(v.x, v.y);
        __half2 b = __floats2half2_rn(v.z, v.w);
        w2[16384 + gt] = make_uint2(hbits(a), hbits(b));
    }
}

// ============================ shared projection body (HMMA trans-A, f16 acc) ============================
// tp[s][o-tile] = sum_c xb[c,s] * w2[o,c] for o in [n0, n0+128)
#define SA2(st) ((uint32_t)((st) * 32768))
#define SB2(st) ((uint32_t)((st) * 32768 + 16384))
__device__ __forceinline__ void projection_body(uint32_t sb,
                                                const __half* __restrict__ xb,
                                                const __half* __restrict__ w2,
                                                __half* tp,
                                                int z, int m0, int n0)
{
    const int tid = threadIdx.x, lane = tid & 31, wid = tid >> 5;
    const int wm = wid & 1, wn = wid >> 1;

    const __half* Abase = xb + (size_t)z * CDIM * SDIM + m0;
    const __half* Bbase = w2 + (size_t)n0 * 256;

    uint32_t acc[4][4][2];
    ZERO_ACCH(acc);

    load_tile_64x128(sb + SA2(0), Abase, SDIM);
    load_tileT<128, 256>(sb + SB2(0), Bbase, 256);
    CP_COMMIT();

    const int KT = 4;
    #pragma unroll
    for (int kt = 0; kt < KT; kt++) {
        if (kt + 1 < KT) {
            load_tile_64x128(sb + SA2((kt + 1) & 1), Abase + (size_t)(kt + 1) * 64 * SDIM, SDIM);
            load_tileT<128, 256>(sb + SB2((kt + 1) & 1), Bbase + (kt + 1) * 64, 256);
            CP_COMMIT();
            CP_WAIT(1);
        } else {
            CP_WAIT(0);
        }
        __syncthreads();
        compute_chunk_At(sb + SA2(kt & 1), sb + SB2(kt & 1), wm, wn, lane, acc);
        __syncthreads();
    }

    // epilogue: acc regs ARE packed half2 -> direct stores
    const int lrow = lane >> 2, lcol2 = (lane & 3) * 2;
    #pragma unroll
    for (int mi = 0; mi < 4; mi++) {
        const int gr0 = m0 + wm * 64 + mi * 16 + lrow;   // s
        #pragma unroll
        for (int ni = 0; ni < 4; ni++) {
            const int col = n0 + wn * 32 + ni * 8 + lcol2;  // o in [0,512)
            *reinterpret_cast<uint32_t*>(tp + ((size_t)z * SDIM + gr0) * 512 + col) = acc[mi][ni][0];
            *reinterpret_cast<uint32_t*>(tp + ((size_t)z * SDIM + gr0 + 8) * 512 + col) = acc[mi][ni][1];
        }
    }
}

// ============================ projections (theta/phi only): grid (2, 32, 4) ============================
__global__ __launch_bounds__(256)
void projections_hmma(const __half* __restrict__ xb,
                      const __half* __restrict__ w2,
                      __half* __restrict__ tp)
{
    extern __shared__ char smem[];
    projection_body(smem_u32(smem), xb, w2, tp,
                    blockIdx.z, blockIdx.y * 128, blockIdx.x * 128);
}

// ============================ fused logits+exp (m-PAIR) AND xp-projection: grid (34, 16, 4) ============================
// bx < 32: logits for n-tile bx, theta tiles m0 = by*256 and m0+128 (shared phi tile).
// bx in {32,33}: xp-projection for o-tile 256 + (bx-32)*128, s-tiles by*256 and by*256+128.
// smem (logits path): T0C0 @0, T0C1 @16K, T1C0 @32K, T1C1 @48K, PC0 @64K, PC1 @80K = 96KB.
#define LT(t, ch) ((uint32_t)(((t) * 2 + (ch)) * 16384))
#define LP(ch)    ((uint32_t)(65536 + (ch) * 16384))
__global__ __launch_bounds__(256)
void logits_xp_hmma(__half* tp,
                    __half* __restrict__ f,
                    float* __restrict__ Z,
                    const __half* __restrict__ xb,
                    const __half* __restrict__ w2)
{
    extern __shared__ char smem[];
    const uint32_t sb = smem_u32(smem);
    const int z = blockIdx.z;
    const int mp0 = blockIdx.y * 256;   // m-pair base

    if (blockIdx.x >= 32) {
        // xp projection path: writes tp[:, 256:512) — disjoint from logits' reads (tp[:, 0:256))
        const int n_o = 256 + (blockIdx.x - 32) * 128;
        projection_body(sb, xb, w2, tp, z, mp0, n_o);
        projection_body(sb, xb, w2, tp, z, mp0 + 128, n_o);
        return;
    }

    // ---- logits path: two theta tiles vs one phi tile ----
    const int tid = threadIdx.x, lane = tid & 31, wid = tid >> 5;
    const int wm = wid & 1, wn = wid >> 1;
    const int n0 = blockIdx.x * 128;

    const __half* A0 = tp + ((size_t)(z * SDIM + mp0)) * 512;          // theta tile 0
    const __half* A1 = tp + ((size_t)(z * SDIM + mp0 + 128)) * 512;    // theta tile 1
    const __half* Bb = tp + ((size_t)(z * SDIM + n0)) * 512 + 128;     // phi

    uint32_t acc0[4][4][2], acc1[4][4][2];
    ZERO_ACCH(acc0);
    ZERO_ACCH(acc1);

    load_tileT<128, 256>(sb + LT(0, 0), A0, 512);
    load_tileT<128, 256>(sb + LT(0, 1), A0 + 64, 512);
    load_tileT<128, 256>(sb + LT(1, 0), A1, 512);
    load_tileT<128, 256>(sb + LT(1, 1), A1 + 64, 512);
    load_tileT<128, 256>(sb + LP(0), Bb, 512);
    load_tileT<128, 256>(sb + LP(1), Bb + 64, 512);
    CP_COMMIT();
    CP_WAIT(0);
    __syncthreads();

    compute_chunk(sb + LT(0, 0), sb + LP(0), wm * 64, wn * 32, lane, acc0);
    compute_chunk(sb + LT(1, 0), sb + LP(0), wm * 64, wn * 32, lane, acc1);
    compute_chunk(sb + LT(0, 1), sb + LP(1), wm * 64, wn * 32, lane, acc0);
    compute_chunk(sb + LT(1, 1), sb + LP(1), wm * 64, wn * 32, lane, acc1);

    const float alpha = 0.08838834764831845f; // 1/sqrt(128)
    const int lrow = lane >> 2, lcol2 = (lane & 3) * 2;

    #pragma unroll
    for (int half = 0; half < 2; half++) {
        uint32_t (*acc)[4][2] = half ? acc1 : acc0;
        const int mb = mp0 + half * 128;
        #pragma unroll
        for (int mi = 0; mi < 4; mi++) {
            const int gr0 = mb + wm * 64 + mi * 16 + lrow;
            const int gr1 = gr0 + 8;
            float rs0 = 0.0f, rs1 = 0.0f;
            #pragma unroll
            for (int ni = 0; ni < 4; ni++) {
                const int col = n0 + wn * 32 + ni * 8 + lcol2;
                const float2 p0 = h2f(acc[mi][ni][0]);   // row gr0: (col, col+1)
                const float2 p1 = h2f(acc[mi][ni][1]);   // row gr1
                float e00 = __expf(p0.x * alpha);
                float e01 = __expf(p0.y * alpha);
                float e10 = __expf(p1.x * alpha);
                float e11 = __expf(p1.y * alpha);
                rs0 += e00 + e01; rs1 += e10 + e11;
                __half2 h0 = __floats2half2_rn(e00, e01);
                __half2 h1 = __floats2half2_rn(e10, e11);
                *reinterpret_cast<uint32_t*>(f + ((size_t)z * SDIM + gr0) * SDIM + col) = hbits(h0);
                *reinterpret_cast<uint32_t*>(f + ((size_t)z * SDIM + gr1) * SDIM + col) = hbits(h1);
            }
            rs0 += __shfl_xor_sync(0xffffffffu, rs0, 1);
            rs0 += __shfl_xor_sync(0xffffffffu, rs0, 2);
            rs1 += __shfl_xor_sync(0xffffffffu, rs1, 1);
            rs1 += __shfl_xor_sync(0xffffffffu, rs1, 2);
            if ((lane & 3) == 0) {
                atomicAdd(&Z[(size_t)z * SDIM + gr0], rs0);
                atomicAdd(&Z[(size_t)z * SDIM + gr1], rs1);
            }
        }
    }
}

// ============================ fused attend+proj (R13-proven, trans-A, f16 acc, 3-stage) ============================
// out[n][o][s] = x[n][o][s] + (1/Z[s]) * sum_t xp[o,t] * f[s,t]
#define ASA(st) ((uint32_t)((st) * 32768))
#define ASB(st) ((uint32_t)((st) * 32768 + 16384))
__global__ __launch_bounds__(256)
void attend_proj_hmma(const __half* __restrict__ tp,
                      const __half* __restrict__ f,
                      const float* __restrict__ Z,
                      const float* __restrict__ x,
                      float* __restrict__ out)
{
    extern __shared__ char smem[];
    const uint32_t sb = smem_u32(smem);
    const int tid = threadIdx.x, lane = tid & 31, wid = tid >> 5;
    const int wm = wid & 1, wn = wid >> 1;
    const int z = blockIdx.z, m0 = blockIdx.y * 128, n0 = blockIdx.x * 128;

    const __half* Abase = tp + (size_t)z * SDIM * 512 + 256 + m0;   // rows t, ld 512
    const __half* Bbase = f + ((size_t)z * SDIM + n0) * SDIM;       // rows s, ld SDIM

    uint32_t acc[4][4][2];
    ZERO_ACCH(acc);

    load_tile_64x128(sb + ASA(0), Abase, 512);
    load_tileT<128, 256>(sb + ASB(0), Bbase, SDIM);
    CP_COMMIT();
    load_tile_64x128(sb + ASA(1), Abase + (size_t)64 * 512, 512);
    load_tileT<128, 256>(sb + ASB(1), Bbase + 64, SDIM);
    CP_COMMIT();

    const int KT = SDIM / 64; // 64
    for (int kt = 0; kt < KT; kt++) {
        if (kt + 1 < KT) { CP_WAIT(1); } else { CP_WAIT(0); }
        __syncthreads();
        if (kt + 2 < KT) {
            const int st = (kt + 2) % 3;
            load_tile_64x128(sb + ASA(st), Abase + (size_t)(kt + 2) * 64 * 512, 512);
            load_tileT<128, 256>(sb + ASB(st), Bbase + (kt + 2) * 64, SDIM);
            CP_COMMIT();
        }
        compute_chunk_At(sb + ASA(kt % 3), sb + ASB(kt % 3), wm, wn, lane, acc);
    }

    // epilogue: rows = o, cols = s; scale by 1/Z[s], add residual x, fp32 out
    const int lrow = lane >> 2, lcol2 = (lane & 3) * 2;
    #pragma unroll
    for (int ni = 0; ni < 4; ni++) {
        const int col = n0 + wn * 32 + ni * 8 + lcol2;   // s (even)
        const float2 zc = *reinterpret_cast<const float2*>(&Z[(size_t)z * SDIM + col]);
        const float izx = 1.0f / zc.x, izy = 1.0f / zc.y;
        #pragma unroll
        for (int mi = 0; mi < 4; mi++) {
            const int gr0 = m0 + wm * 64 + mi * 16 + lrow;   // o
            const int gr1 = gr0 + 8;
            const float2 a0 = h2f(acc[mi][ni][0]);   // row gr0: (col, col+1)
            const float2 a1 = h2f(acc[mi][ni][1]);   // row gr1
            const float2 x0 = *reinterpret_cast<const float2*>(x + ((size_t)z * CDIM + gr0) * SDIM + col);
            const float2 x1 = *reinterpret_cast<const float2*>(x + ((size_t)z * CDIM + gr1) * SDIM + col);
            float2 v0 = make_float2(a0.x * izx + x0.x, a0.y * izy + x0.y);
            float2 v1 = make_float2(a1.x * izx + x1.x, a1.y * izy + x1.y);
            *reinterpret_cast<float2*>(out + ((size_t)z * CDIM + gr0) * SDIM + col) = v0;
            *reinterpret_cast<float2*>(out + ((size_t)z * CDIM + gr1) * SDIM + col) = v1;
        }
    }
}

// ============================ launch ============================
extern "C" void kernel_launch(void* const* d_in, const int* in_sizes, int n_in,
                              void* d_out, int out_size)
{
    const float* x       = (const float*)d_in[0];
    const float* theta_w = (const float*)d_in[1];
    const float* phi_w   = (const float*)d_in[2];
    const float* proj_w  = (const float*)d_in[3];
    float* out = (float*)d_out;

    __half *tp, *f, *xb, *w2;
    float *Z;
    cudaGetSymbolAddress((void**)&tp, g_tp);
    cudaGetSymbolAddress((void**)&f,  g_f);
    cudaGetSymbolAddress((void**)&xb, g_xb);
    cudaGetSymbolAddress((void**)&w2, g_w2);
    cudaGetSymbolAddress((void**)&Z,  g_Z);

    cudaFuncSetAttribute(projections_hmma, cudaFuncAttributeMaxDynamicSharedMemorySize, 65536);
    cudaFuncSetAttribute(logits_xp_hmma,   cudaFuncAttributeMaxDynamicSharedMemorySize, 98304);
    cudaFuncSetAttribute(attend_proj_hmma, cudaFuncAttributeMaxDynamicSharedMemorySize, 98304);

    // 0: fp16 conversions + Z zero
    prep_h<<<1024, 256>>>((const float4*)x, (const float4*)theta_w, (const float4*)phi_w,
                          (const float4*)proj_w, (uint2*)xb, (uint2*)w2, Z,
                          (int)((size_t)NBATCH * CDIM * SDIM / 4));

    // 1: theta + phi projections only (o-tiles 0,1)
    projections_hmma<<<dim3(2, 32, 4), 256, 65536>>>(xb, w2, tp);

    // 2: fused logits->exp (m-pair, shared phi) + xp-projection in ONE launch
    logits_xp_hmma<<<dim3(34, 16, 4), 256, 98304>>>(tp, f, Z, xb, w2);

    // 3: fused attend + projection + residual + 1/Z
    attend_proj_hmma<<<dim3(32, 2, 4), 256, 98304>>>(tp, f, Z, x, out);
}